// round 11
// baseline (speedup 1.0000x reference)
#include <cuda_runtime.h>

#define NUM_SKILLS 300
#define EMB 256
#define CD 64
#define BB 512
#define SS 200
#define RPB_OUT 64                 // rows per block in store kernel (flat rows)
#define NSEG 7                     // 7 segments of 32 cover 224 >= 200

// Scratch (no allocations allowed).
__device__ float4 g_scal[BB * SS];         // {qf, att, mast, valid}
__device__ float  g_A[EMB], g_B[EMB], g_C[EMB], g_D[EMB];

// ---------------------------------------------------------------------------
// K1, grid 544.
// Blocks 0..511: counts for one batch row, warp-segment formulation.
//   Within-segment running counts: __match_any_sync + popc(lanemask_le).
//   Cross-segment: per-warp histogram (att | cor<<16) via shared atomics.
// Blocks 512..543: einsum-collapse coefficients, one warp per e:
//   out[b,s,e] = qf*A[e] + att*B[e] + mast*C[e] + valid*D[e]
// ---------------------------------------------------------------------------
__global__ void __launch_bounds__(256) prep_kernel(
    const int* __restrict__ q, const int* __restrict__ r,
    const float* __restrict__ skill_w, const float* __restrict__ skill_b,
    const float* __restrict__ att_w,   const float* __restrict__ att_b,
    const float* __restrict__ mast_w,  const float* __restrict__ mast_b,
    const float* __restrict__ proj_w,  const float* __restrict__ proj_b)
{
    const int blk  = blockIdx.x;
    const int t    = threadIdx.x;
    const int w    = t >> 5;
    const int lane = t & 31;

    if (blk < BB) {
        __shared__ unsigned hist[NSEG][NUM_SKILLS + 4];   // att | cor<<16

        unsigned* hz = &hist[0][0];
        for (int i = t; i < NSEG * (NUM_SKILLS + 4); i += 256) hz[i] = 0;

        int valid = 0, key = 0x8000 | t, rb = 0;
        if (t < SS) {
            const int qraw = q[blk * SS + t];
            valid = (qraw >= 0) & (qraw < NUM_SKILLS);
            if (valid) {
                key = qraw;
                rb  = r[blk * SS + t] & 1;
            }
        }
        __syncthreads();   // histograms zeroed

        // within-segment running counts (self included)
        const unsigned mask  = __match_any_sync(0xFFFFFFFFu, key);
        const unsigned rball = __ballot_sync(0xFFFFFFFFu, rb);
        const unsigned le    = (lane == 31) ? 0xFFFFFFFFu : ((2u << lane) - 1u);
        int att = __popc(mask & le);
        int cor = __popc(mask & le & rball);

        if (valid) atomicAdd(&hist[w][key], 1u | ((unsigned)rb << 16));
        __syncthreads();

        if (t < SS && valid) {
            unsigned acc = 0;
            for (int gp = 0; gp < w; ++gp) acc += hist[gp][key];
            att += (int)(acc & 0xFFFFu);
            cor += (int)(acc >> 16);
            const float attf = (float)att;
            g_scal[blk * SS + t] =
                make_float4((float)key, attf, (float)cor / fmaxf(attf, 1.0f), 1.0f);
        } else if (t < SS) {
            g_scal[blk * SS + t] = make_float4(0.f, 0.f, 0.f, 0.f);
        }
    } else {
        // ---- coefficients: e = (blk-512)*8 + warp ----
        const int e   = (blk - BB) * 8 + w;      // 0..255
        const int chi = lane + 32;

        const float wlo = (lane < 21) ? skill_w[lane] : att_w[lane - 21];
        const float blo = (lane < 21) ? skill_b[lane] : att_b[lane - 21];
        const float whi = (chi  < 42) ? att_w[chi - 21] : mast_w[chi - 42];
        const float bhi = (chi  < 42) ? att_b[chi - 21] : mast_b[chi - 42];

        const float p0 = proj_w[e * CD + lane];
        const float p1 = proj_w[e * CD + chi];

        const bool loA = lane < 21;
        const bool hiB = chi  < 42;

        float av = loA ? p0 * wlo : 0.0f;
        float bv = (loA ? 0.0f : p0 * wlo) + (hiB ? p1 * whi : 0.0f);
        float cv = hiB ? 0.0f : p1 * whi;
        float dv = fmaf(p0, blo, p1 * bhi);

        #pragma unroll
        for (int off = 16; off > 0; off >>= 1) {
            av += __shfl_xor_sync(0xFFFFFFFF, av, off);
            bv += __shfl_xor_sync(0xFFFFFFFF, bv, off);
            cv += __shfl_xor_sync(0xFFFFFFFF, cv, off);
            dv += __shfl_xor_sync(0xFFFFFFFF, dv, off);
        }
        if (lane == 0) {
            g_A[e] = av; g_B[e] = bv; g_C[e] = cv;
            g_D[e] = dv + proj_b[e];
        }
    }
}

// ---------------------------------------------------------------------------
// K2: pure store kernel. 1600 blocks x 256 threads, 64 flat rows per block.
// The store path is at its L1 sector floor (~11.5us of sector work chip-wide);
// the lever is UTILIZATION: __launch_bounds__(256, 8) forces <=32 regs ->
// 8 resident blocks/SM = 64 warps = 100% occupancy cap, filling the latency
// bubbles that currently leave L1 36% idle.
// ---------------------------------------------------------------------------
__global__ void __launch_bounds__(256, 8) out_kernel(float* __restrict__ out)
{
    __shared__ float4 sscal[RPB_OUT];

    const int t   = threadIdx.x;
    const int e4  = t & 63;
    const int l4  = t >> 6;                      // 0..3
    const int bs0 = blockIdx.x * RPB_OUT;        // flat row base

    const float4 a  = __ldg(&reinterpret_cast<const float4*>(g_A)[e4]);
    const float4 bc = __ldg(&reinterpret_cast<const float4*>(g_B)[e4]);
    const float4 cc = __ldg(&reinterpret_cast<const float4*>(g_C)[e4]);
    const float4 dc = __ldg(&reinterpret_cast<const float4*>(g_D)[e4]);

    if (t < RPB_OUT) sscal[t] = g_scal[bs0 + t];
    __syncthreads();

    float4* __restrict__ out4 = reinterpret_cast<float4*>(out);
    const int base = bs0 * (EMB / 4) + e4;

    #pragma unroll
    for (int i = 0; i < RPB_OUT / 4; ++i) {
        const int row = l4 + i * 4;              // 0..63, uniform per warp
        const float4 s = sscal[row];             // LDS broadcast
        float4 o;
        o.x = fmaf(s.x, a.x, fmaf(s.y, bc.x, fmaf(s.z, cc.x, s.w * dc.x)));
        o.y = fmaf(s.x, a.y, fmaf(s.y, bc.y, fmaf(s.z, cc.y, s.w * dc.y)));
        o.z = fmaf(s.x, a.z, fmaf(s.y, bc.z, fmaf(s.z, cc.z, s.w * dc.z)));
        o.w = fmaf(s.x, a.w, fmaf(s.y, bc.w, fmaf(s.z, cc.w, s.w * dc.w)));
        out4[base + row * (EMB / 4)] = o;        // offset is compile-time imm
    }
}

// Input order (metadata): 0=q 1=r 2=qry(unused) 3=skill_w 4=skill_b
// 5=att_w 6=att_b 7=mast_w 8=mast_b 9=proj_w 10=proj_b
extern "C" void kernel_launch(void* const* d_in, const int* in_sizes, int n_in,
                              void* d_out, int out_size)
{
    const int*   q       = (const int*)d_in[0];
    const int*   r       = (const int*)d_in[1];
    const float* skill_w = (const float*)d_in[3];
    const float* skill_b = (const float*)d_in[4];
    const float* att_w   = (const float*)d_in[5];
    const float* att_b   = (const float*)d_in[6];
    const float* mast_w  = (const float*)d_in[7];
    const float* mast_b  = (const float*)d_in[8];
    const float* proj_w  = (const float*)d_in[9];
    const float* proj_b  = (const float*)d_in[10];
    float* out = (float*)d_out;

    prep_kernel<<<BB + EMB / 8, 256>>>(q, r, skill_w, skill_b, att_w, att_b,
                                       mast_w, mast_b, proj_w, proj_b);

    out_kernel<<<(BB * SS) / RPB_OUT, 256>>>(out);   // 1600 blocks
}

// round 13
// speedup vs baseline: 1.0288x; 1.0288x over previous
#include <cuda_runtime.h>

#define NUM_SKILLS 300
#define EMB 256
#define CD 64
#define BB 512
#define SS 200
#define RPB_OUT 64                 // rows per block in store kernel (flat rows)
#define NSEG 7                     // 7 segments of 32 cover 224 >= 200

// Scratch (no allocations allowed).
__device__ float4 g_scal[BB * SS];         // {qf, att, mast, valid}
__device__ float  g_A[EMB], g_B[EMB], g_C[EMB], g_D[EMB];

// ---------------------------------------------------------------------------
// K1, grid 544. Triggers dependent launch immediately (PDL): the store
// kernel's launch+setup overlaps this kernel's execution.
// Blocks 0..511: counts for one batch row (match_any + lanemask_le within
//   32-wide segments; cross-segment via per-warp packed histograms).
// Blocks 512..543: einsum-collapse coefficients, one warp per e:
//   out[b,s,e] = qf*A[e] + att*B[e] + mast*C[e] + valid*D[e]
// ---------------------------------------------------------------------------
__global__ void __launch_bounds__(256) prep_kernel(
    const int* __restrict__ q, const int* __restrict__ r,
    const float* __restrict__ skill_w, const float* __restrict__ skill_b,
    const float* __restrict__ att_w,   const float* __restrict__ att_b,
    const float* __restrict__ mast_w,  const float* __restrict__ mast_b,
    const float* __restrict__ proj_w,  const float* __restrict__ proj_b)
{
#if __CUDA_ARCH__ >= 900
    asm volatile("griddepcontrol.launch_dependents;");   // let K2 launch now
#endif
    const int blk  = blockIdx.x;
    const int t    = threadIdx.x;
    const int w    = t >> 5;
    const int lane = t & 31;

    if (blk < BB) {
        __shared__ unsigned hist[NSEG][NUM_SKILLS + 4];   // att | cor<<16

        // zero histograms with 64-bit stores (7*304/2 = 1064 u2 words)
        uint2* hz2 = reinterpret_cast<uint2*>(&hist[0][0]);
        #pragma unroll
        for (int i = 0; i < 5; ++i) {
            const int idx = t + i * 256;
            if (idx < NSEG * (NUM_SKILLS + 4) / 2) hz2[idx] = make_uint2(0u, 0u);
        }

        int valid = 0, key = 0x8000 | t, rb = 0;
        if (t < SS) {
            const int qraw = q[blk * SS + t];
            valid = (qraw >= 0) & (qraw < NUM_SKILLS);
            if (valid) {
                key = qraw;
                rb  = r[blk * SS + t] & 1;
            }
        }
        __syncthreads();   // histograms zeroed

        // within-segment running counts (self included)
        const unsigned mask  = __match_any_sync(0xFFFFFFFFu, key);
        const unsigned rball = __ballot_sync(0xFFFFFFFFu, rb);
        const unsigned le    = (lane == 31) ? 0xFFFFFFFFu : ((2u << lane) - 1u);
        int att = __popc(mask & le);
        int cor = __popc(mask & le & rball);

        if (valid) atomicAdd(&hist[w][key], 1u | ((unsigned)rb << 16));
        __syncthreads();

        if (t < SS && valid) {
            unsigned acc = 0;
            for (int gp = 0; gp < w; ++gp) acc += hist[gp][key];
            att += (int)(acc & 0xFFFFu);
            cor += (int)(acc >> 16);
            const float attf = (float)att;
            g_scal[blk * SS + t] =
                make_float4((float)key, attf, (float)cor / fmaxf(attf, 1.0f), 1.0f);
        } else if (t < SS) {
            g_scal[blk * SS + t] = make_float4(0.f, 0.f, 0.f, 0.f);
        }
    } else {
        // ---- coefficients: e = (blk-512)*8 + warp ----
        const int e   = (blk - BB) * 8 + w;      // 0..255
        const int chi = lane + 32;

        const float wlo = (lane < 21) ? skill_w[lane] : att_w[lane - 21];
        const float blo = (lane < 21) ? skill_b[lane] : att_b[lane - 21];
        const float whi = (chi  < 42) ? att_w[chi - 21] : mast_w[chi - 42];
        const float bhi = (chi  < 42) ? att_b[chi - 21] : mast_b[chi - 42];

        const float p0 = proj_w[e * CD + lane];
        const float p1 = proj_w[e * CD + chi];

        const bool loA = lane < 21;
        const bool hiB = chi  < 42;

        float av = loA ? p0 * wlo : 0.0f;
        float bv = (loA ? 0.0f : p0 * wlo) + (hiB ? p1 * whi : 0.0f);
        float cv = hiB ? 0.0f : p1 * whi;
        float dv = fmaf(p0, blo, p1 * bhi);

        #pragma unroll
        for (int off = 16; off > 0; off >>= 1) {
            av += __shfl_xor_sync(0xFFFFFFFF, av, off);
            bv += __shfl_xor_sync(0xFFFFFFFF, bv, off);
            cv += __shfl_xor_sync(0xFFFFFFFF, cv, off);
            dv += __shfl_xor_sync(0xFFFFFFFF, dv, off);
        }
        if (lane == 0) {
            g_A[e] = av; g_B[e] = bv; g_C[e] = cv;
            g_D[e] = dv + proj_b[e];
        }
    }
}

// ---------------------------------------------------------------------------
// K2: pure store kernel (R10 shape — measured 17.7us, at the L2-write
// ceiling). PDL: index setup happens before griddepcontrol.wait, so this
// kernel's launch+preamble overlaps prep's execution; the wait guarantees
// all of prep's g_scal/g_A..g_D writes are visible before the first load.
// ---------------------------------------------------------------------------
__global__ void __launch_bounds__(256) out_kernel(float* __restrict__ out)
{
    __shared__ float4 sscal[RPB_OUT];

    const int t   = threadIdx.x;
    const int e4  = t & 63;
    const int l4  = t >> 6;                      // 0..3
    const int bs0 = blockIdx.x * RPB_OUT;        // flat row base
    float4* __restrict__ out4 = reinterpret_cast<float4*>(out);
    const int base = bs0 * (EMB / 4) + e4;

#if __CUDA_ARCH__ >= 900
    asm volatile("griddepcontrol.wait;" ::: "memory");   // prep fully done
#endif

    const float4 a  = __ldg(&reinterpret_cast<const float4*>(g_A)[e4]);
    const float4 bc = __ldg(&reinterpret_cast<const float4*>(g_B)[e4]);
    const float4 cc = __ldg(&reinterpret_cast<const float4*>(g_C)[e4]);
    const float4 dc = __ldg(&reinterpret_cast<const float4*>(g_D)[e4]);

    if (t < RPB_OUT) sscal[t] = g_scal[bs0 + t];
    __syncthreads();

    #pragma unroll
    for (int i = 0; i < RPB_OUT / 4; ++i) {
        const int row = l4 + i * 4;              // 0..63, uniform per warp
        const float4 s = sscal[row];             // LDS broadcast
        float4 o;
        o.x = fmaf(s.x, a.x, fmaf(s.y, bc.x, fmaf(s.z, cc.x, s.w * dc.x)));
        o.y = fmaf(s.x, a.y, fmaf(s.y, bc.y, fmaf(s.z, cc.y, s.w * dc.y)));
        o.z = fmaf(s.x, a.z, fmaf(s.y, bc.z, fmaf(s.z, cc.z, s.w * dc.z)));
        o.w = fmaf(s.x, a.w, fmaf(s.y, bc.w, fmaf(s.z, cc.w, s.w * dc.w)));
        out4[base + row * (EMB / 4)] = o;
    }
}

// Input order (metadata): 0=q 1=r 2=qry(unused) 3=skill_w 4=skill_b
// 5=att_w 6=att_b 7=mast_w 8=mast_b 9=proj_w 10=proj_b
extern "C" void kernel_launch(void* const* d_in, const int* in_sizes, int n_in,
                              void* d_out, int out_size)
{
    const int*   q       = (const int*)d_in[0];
    const int*   r       = (const int*)d_in[1];
    const float* skill_w = (const float*)d_in[3];
    const float* skill_b = (const float*)d_in[4];
    const float* att_w   = (const float*)d_in[5];
    const float* att_b   = (const float*)d_in[6];
    const float* mast_w  = (const float*)d_in[7];
    const float* mast_b  = (const float*)d_in[8];
    const float* proj_w  = (const float*)d_in[9];
    const float* proj_b  = (const float*)d_in[10];
    float* out = (float*)d_out;

    prep_kernel<<<BB + EMB / 8, 256>>>(q, r, skill_w, skill_b, att_w, att_b,
                                       mast_w, mast_b, proj_w, proj_b);

    // Dependent launch with programmatic stream serialization (PDL):
    // overlaps out_kernel's launch/preamble with prep's execution. If PDL
    // is unavailable the attribute is ignored and this is a normal ordered
    // launch; griddepcontrol.wait then completes immediately.
    cudaLaunchConfig_t cfg = {};
    cfg.gridDim  = dim3((BB * SS) / RPB_OUT, 1, 1);   // 1600 blocks
    cfg.blockDim = dim3(256, 1, 1);
    cfg.dynamicSmemBytes = 0;
    cfg.stream = 0;
    cudaLaunchAttribute attr[1];
    attr[0].id = cudaLaunchAttributeProgrammaticStreamSerialization;
    attr[0].val.programmaticStreamSerializationAllowed = 1;
    cfg.attrs = attr;
    cfg.numAttrs = 1;
    if (cudaLaunchKernelEx(&cfg, out_kernel, (float*)d_out) != cudaSuccess) {
        // Fallback: plain ordered launch (PDL wait degenerates to no-op).
        out_kernel<<<(BB * SS) / RPB_OUT, 256>>>((float*)d_out);
    }
}